// round 1
// baseline (speedup 1.0000x reference)
#include <cuda_runtime.h>
#include <cuda_fp16.h>

#define BATCH 64
#define NIN   2048
#define DIN   16
#define NOUT  32
#define DOUT  32
#define JD    (NOUT*DOUT)   // 1024

// Scratch (device globals — no allocation allowed)
__device__ __half2 g_uhat[(size_t)BATCH * NIN * (JD/2)];  // [b][i][jd/2], 268 MB
__device__ float   g_s[BATCH * JD];
__device__ float   g_vsum[BATCH * JD];

__global__ void kernelZero() {
    int t = blockIdx.x * 1024 + threadIdx.x;
    g_s[t] = 0.f;
    g_vsum[t] = 0.f;
}

// u_hat[b,i,jd] = sum_k W[i,jd,k] * x[b,i,k]; store fp16.
// One block per i. Thread t owns jd0=2t, jd1=2t+1 (W rows in registers),
// loops over all 64 batches reusing W.
__global__ void __launch_bounds__(512) kernelU(const float* __restrict__ x,
                                               const float* __restrict__ W) {
    __shared__ float xs[BATCH * DIN];   // 4 KB
    const int i = blockIdx.x;
    const int t = threadIdx.x;

    // stage x[:, i, :]
    for (int r = t; r < BATCH * DIN; r += 512) {
        int b = r >> 4, k = r & 15;
        xs[r] = x[(size_t)b * (NIN * DIN) + (size_t)i * DIN + k];
    }

    // W rows for jd0 = 2t, jd1 = 2t+1 (16 floats each) via float4
    const float4* W4 = reinterpret_cast<const float4*>(W + (size_t)i * JD * DIN);
    float4 wa[4], wb[4];
#pragma unroll
    for (int q = 0; q < 4; q++) { wa[q] = W4[8 * t + q]; wb[q] = W4[8 * t + 4 + q]; }
    float w0[DIN], w1[DIN];
#pragma unroll
    for (int q = 0; q < 4; q++) {
        w0[4*q+0] = wa[q].x; w0[4*q+1] = wa[q].y; w0[4*q+2] = wa[q].z; w0[4*q+3] = wa[q].w;
        w1[4*q+0] = wb[q].x; w1[4*q+1] = wb[q].y; w1[4*q+2] = wb[q].z; w1[4*q+3] = wb[q].w;
    }
    __syncthreads();

    for (int b = 0; b < BATCH; b++) {
        const float* xb = xs + b * DIN;
        float a0 = 0.f, a1 = 0.f;
#pragma unroll
        for (int k = 0; k < DIN; k++) {
            float xv = xb[k];
            a0 = fmaf(w0[k], xv, a0);
            a1 = fmaf(w1[k], xv, a1);
        }
        g_uhat[((size_t)b * NIN + i) * (JD/2) + t] = __floats2half2_rn(a0, a1);
    }
}

// Iter-0: s0[b,jd] = sum_i u_hat[b,i,jd]  (uniform c folded in at squash via pre=1/32)
__global__ void __launch_bounds__(512) kernelR0() {
    const int b = blockIdx.x;
    const int chunk = blockIdx.y;         // 16 chunks of 128 i's
    const int t = threadIdx.x;
    float a0 = 0.f, a1 = 0.f;
    size_t base = ((size_t)b * NIN + (size_t)chunk * 128) * (JD/2) + t;
    for (int ii = 0; ii < 128; ii++) {
        float2 f = __half22float2(g_uhat[base + (size_t)ii * (JD/2)]);
        a0 += f.x; a1 += f.y;
    }
    atomicAdd(&g_s[b * JD + 2 * t], a0);
    atomicAdd(&g_s[b * JD + 2 * t + 1], a1);
}

// v = squash(pre * s); vsum += v; s = 0; write v to out
__global__ void __launch_bounds__(1024) kernelSquash(float pre, float* __restrict__ vout) {
    const int b = blockIdx.x;
    const int t = threadIdx.x;            // t = jd; warp = one j (32 d's)
    float s = g_s[b * JD + t] * pre;
    float s2 = s * s;
#pragma unroll
    for (int off = 16; off; off >>= 1) s2 += __shfl_xor_sync(0xffffffffu, s2, off);
    float scale = (s2 / (1.f + s2 + 1e-9f)) * rsqrtf(s2 + 1e-9f);
    float v = s * scale;
    vout[b * JD + t]   = v;
    g_vsum[b * JD + t] += v;
    g_s[b * JD + t]    = 0.f;
}

// Routing iter (k>=1): per (b,i): logit[j] = sum_d u_hat[b,i,j,d]*vsum[b,j,d];
// c = softmax_j(logit); s[b,j,d] += c[j]*u_hat[b,i,j,d]
__global__ void __launch_bounds__(256) kernelRoute() {
    const int b = blockIdx.x;
    const int chunk = blockIdx.y;         // 32 chunks of 64 i's
    const int t = threadIdx.x;

    __shared__ float vs[JD];              // vsum[b]
    __shared__ float cl[NOUT];            // logits
    __shared__ float cc[NOUT];            // softmax coefficients

    for (int r = t; r < JD; r += 256) vs[r] = g_vsum[b * JD + r];
    __syncthreads();

    // thread t -> j = t/8, d0 = (t%8)*4  (4 d's, two half2 loads)
    const int j = t >> 3;
    const int d0 = (t & 7) * 4;
    const int jd0 = j * DOUT + d0;
    float vv[4];
#pragma unroll
    for (int q = 0; q < 4; q++) vv[q] = vs[jd0 + q];

    float acc[4] = {0.f, 0.f, 0.f, 0.f};

    for (int ii = 0; ii < 64; ii++) {
        size_t base = ((size_t)b * NIN + (size_t)chunk * 64 + ii) * (JD/2);
        __half2 h0 = g_uhat[base + (jd0 >> 1)];
        __half2 h1 = g_uhat[base + (jd0 >> 1) + 1];
        float u0 = __low2float(h0), u1 = __high2float(h0);
        float u2 = __low2float(h1), u3 = __high2float(h1);

        float p = u0 * vv[0] + u1 * vv[1] + u2 * vv[2] + u3 * vv[3];
        p += __shfl_xor_sync(0xffffffffu, p, 4);
        p += __shfl_xor_sync(0xffffffffu, p, 2);
        p += __shfl_xor_sync(0xffffffffu, p, 1);
        if ((t & 7) == 0) cl[j] = p;
        __syncthreads();

        if (t < 32) {
            float l = cl[t];
            float m = l;
#pragma unroll
            for (int off = 16; off; off >>= 1) m = fmaxf(m, __shfl_xor_sync(0xffffffffu, m, off));
            float e = __expf(l - m);
            float se = e;
#pragma unroll
            for (int off = 16; off; off >>= 1) se += __shfl_xor_sync(0xffffffffu, se, off);
            cc[t] = e / se;
        }
        __syncthreads();

        float c = cc[j];
        acc[0] = fmaf(c, u0, acc[0]);
        acc[1] = fmaf(c, u1, acc[1]);
        acc[2] = fmaf(c, u2, acc[2]);
        acc[3] = fmaf(c, u3, acc[3]);
        // next iteration's cl-writes are ordered after this sync pair; no extra barrier
    }

#pragma unroll
    for (int q = 0; q < 4; q++) atomicAdd(&g_s[b * JD + jd0 + q], acc[q]);
}

extern "C" void kernel_launch(void* const* d_in, const int* in_sizes, int n_in,
                              void* d_out, int out_size) {
    const float* x = (const float*)d_in[0];   // [64, 2048, 16]
    const float* W = (const float*)d_in[1];   // [1, 2048, 32, 32, 16]
    float* out = (float*)d_out;               // [64, 32, 32]

    kernelZero<<<64, 1024>>>();
    kernelU<<<2048, 512>>>(x, W);
    kernelR0<<<dim3(64, 16), 512>>>();
    kernelSquash<<<64, 1024>>>(1.f / 32.f, out);   // iter 0
    kernelRoute<<<dim3(64, 32), 256>>>();
    kernelSquash<<<64, 1024>>>(1.f, out);          // iter 1
    kernelRoute<<<dim3(64, 32), 256>>>();
    kernelSquash<<<64, 1024>>>(1.f, out);          // iter 2 (final v in d_out)
}